// round 3
// baseline (speedup 1.0000x reference)
#include <cuda_runtime.h>

// Problem constants (fixed by the reference):
//   B=64, T=200 -> 12800 tokens
//   D_SEM=768, D_PROMPT=384 -> K=1152
//   D_MODEL=2048 -> N
//   NUM_ITEMS=100000
// Inputs (metadata order):
//   d_in[0] batch_item_ids_padded  int32  [12800]
//   d_in[1] batch_lengths          int32  [64]      (unused: validity == id in range)
//   d_in[2] E_sem                  f32    [100000*768]
//   d_in[3] v_prompt               f32    [100000*384]
//   d_in[4] proj_w                 f32    [2048*1152]
// Output (float32, concatenated):
//   embeds [12800*2048], amask [12800], tok_item_ids [12800]

#define TOKENS      12800
#define K_DIM       1152
#define D_SEM_DIM   768
#define D_PROMPT_DIM 384
#define N_DIM       2048
#define NUM_ITEMS_C 100000

#define BM 64
#define BN 128
#define BK 16
#define AS_STRIDE 68    // BM + 4 pad, keeps 16B alignment, breaks bank conflicts on STS
#define WS_STRIDE 132   // BN + 4 pad

__global__ __launch_bounds__(256, 4)
void gather_gemm_kernel(const int*   __restrict__ ids,
                        const float* __restrict__ E_sem,
                        const float* __restrict__ v_prompt,
                        const float* __restrict__ W,     // [N_DIM, K_DIM] row-major
                        float*       __restrict__ out)
{
    __shared__ float As[BK * AS_STRIDE];
    __shared__ float Ws[BK * WS_STRIDE];
    __shared__ int   s_id[BM];

    const int tid = threadIdx.x;
    const int i0  = blockIdx.y * BM;   // token tile start
    const int n0  = blockIdx.x * BN;   // d_model tile start

    // Per-row validity: matches reference (ids >= 0) & (ids < num_items)
    if (tid < BM) {
        int id = ids[i0 + tid];
        s_id[tid] = (id >= 0 && id < NUM_ITEMS_C) ? id : -1;
    }
    __syncthreads();
    int any_valid = __syncthreads_or(tid < BM && s_id[tid] >= 0);

    if (!any_valid) {
        // Whole tile is padding: embeds are zeros. Fast path.
        const float4 z = make_float4(0.f, 0.f, 0.f, 0.f);
        #pragma unroll
        for (int v = tid; v < BM * BN / 4; v += 256) {
            int r = v >> 5;           // v / (BN/4)
            int c = v & 31;           // v % (BN/4)
            *(float4*)&out[(size_t)(i0 + r) * N_DIM + n0 + c * 4] = z;
        }
        return;
    }

    const int ty = tid >> 4;          // 0..15  (row group, 4 rows each)
    const int tx = tid & 15;          // 0..15  (col group, 8 cols each)

    // Loader mapping
    const int arow   = tid >> 2;      // 0..63
    const int achunk = tid & 3;       // 0..3  (4 floats each -> 16 k per row)
    const int a_id   = s_id[arow];

    float acc[4][8];
    #pragma unroll
    for (int i = 0; i < 4; i++)
        #pragma unroll
        for (int j = 0; j < 8; j++)
            acc[i][j] = 0.f;

    for (int k0 = 0; k0 < K_DIM; k0 += BK) {
        // ---- load A tile (gathered, transposed into shared) ----
        // BK=16 slabs never straddle the sem/prompt boundary (768 % 16 == 0).
        float4 av;
        if (a_id < 0) {
            av = make_float4(0.f, 0.f, 0.f, 0.f);
        } else if (k0 < D_SEM_DIM) {
            av = *(const float4*)&E_sem[(size_t)a_id * D_SEM_DIM + k0 + achunk * 4];
        } else {
            av = *(const float4*)&v_prompt[(size_t)a_id * D_PROMPT_DIM + (k0 - D_SEM_DIM) + achunk * 4];
        }
        As[(achunk * 4 + 0) * AS_STRIDE + arow] = av.x;
        As[(achunk * 4 + 1) * AS_STRIDE + arow] = av.y;
        As[(achunk * 4 + 2) * AS_STRIDE + arow] = av.z;
        As[(achunk * 4 + 3) * AS_STRIDE + arow] = av.w;

        // ---- load W tile (transposed into shared), 2 n-rows per thread ----
        #pragma unroll
        for (int r = 0; r < 2; r++) {
            int wrow = (tid >> 2) + r * 64;   // 0..127
            float4 wv = *(const float4*)&W[(size_t)(n0 + wrow) * K_DIM + k0 + achunk * 4];
            Ws[(achunk * 4 + 0) * WS_STRIDE + wrow] = wv.x;
            Ws[(achunk * 4 + 1) * WS_STRIDE + wrow] = wv.y;
            Ws[(achunk * 4 + 2) * WS_STRIDE + wrow] = wv.z;
            Ws[(achunk * 4 + 3) * WS_STRIDE + wrow] = wv.w;
        }
        __syncthreads();

        // ---- compute ----
        #pragma unroll
        for (int k = 0; k < BK; k++) {
            float4 a4 = *(const float4*)&As[k * AS_STRIDE + ty * 4];
            float4 w0 = *(const float4*)&Ws[k * WS_STRIDE + tx * 8];
            float4 w1 = *(const float4*)&Ws[k * WS_STRIDE + tx * 8 + 4];
            float a[4] = {a4.x, a4.y, a4.z, a4.w};
            float w[8] = {w0.x, w0.y, w0.z, w0.w, w1.x, w1.y, w1.z, w1.w};
            #pragma unroll
            for (int i = 0; i < 4; i++)
                #pragma unroll
                for (int j = 0; j < 8; j++)
                    acc[i][j] = fmaf(a[i], w[j], acc[i][j]);
        }
        __syncthreads();
    }

    // ---- epilogue: invalid rows had zeroed A so acc == 0 already ----
    #pragma unroll
    for (int i = 0; i < 4; i++) {
        size_t row = (size_t)(i0 + ty * 4 + i);
        float* o = out + row * N_DIM + n0 + tx * 8;
        *(float4*)(o    ) = make_float4(acc[i][0], acc[i][1], acc[i][2], acc[i][3]);
        *(float4*)(o + 4) = make_float4(acc[i][4], acc[i][5], acc[i][6], acc[i][7]);
    }
}

__global__ void meta_kernel(const int* __restrict__ ids, float* __restrict__ out)
{
    int i = blockIdx.x * 256 + threadIdx.x;
    if (i < TOKENS) {
        int id = ids[i];
        bool valid = (id >= 0 && id < NUM_ITEMS_C);
        const size_t base = (size_t)TOKENS * N_DIM;
        out[base + i]          = valid ? 1.0f : 0.0f;          // amask
        out[base + TOKENS + i] = valid ? (float)id : -1.0f;    // tok_item_ids
    }
}

extern "C" void kernel_launch(void* const* d_in, const int* in_sizes, int n_in,
                              void* d_out, int out_size)
{
    const int*   ids      = (const int*)  d_in[0];
    // d_in[1] = batch_lengths (unused; validity derivable from ids)
    const float* E_sem    = (const float*)d_in[2];
    const float* v_prompt = (const float*)d_in[3];
    const float* W        = (const float*)d_in[4];
    float*       out      = (float*)d_out;

    dim3 grid(N_DIM / BN, TOKENS / BM);   // (16, 200)
    gather_gemm_kernel<<<grid, 256>>>(ids, E_sem, v_prompt, W, out);
    meta_kernel<<<(TOKENS + 255) / 256, 256>>>(ids, out);
}

// round 6
// speedup vs baseline: 3.2503x; 3.2503x over previous
#include <cuda_runtime.h>
#include <cuda_bf16.h>
#include <cstdint>

// Problem constants
#define TOKENS       12800
#define K_DIM        1152
#define D_SEM_DIM    768
#define D_PROMPT_DIM 384
#define N_DIM        2048
#define NUM_ITEMS_C  100000

// GEMM tiling (virtual K = 3 * K_DIM via hi/lo split terms)
#define BM      128
#define BN      256
#define BK      32
#define NSLAB_PER_TERM (K_DIM / BK)        // 36
#define NSLAB   (3 * NSLAB_PER_TERM)       // 108
#define STAGES  4

#define A_BYTES     (BM * BK * 2)          // 8192  (row stride 64 B)
#define B_BYTES     (BN * BK * 2)          // 16384
#define STAGE_BYTES (A_BYTES + B_BYTES)    // 24576
#define SMEM_TOTAL  (STAGES * STAGE_BYTES) // 98304

// bf16 hi/lo splits of gathered A and of W
__device__ __align__(256) __nv_bfloat16 g_Ah[(size_t)TOKENS * K_DIM];
__device__ __align__(256) __nv_bfloat16 g_Al[(size_t)TOKENS * K_DIM];
__device__ __align__(256) __nv_bfloat16 g_Wh[(size_t)N_DIM * K_DIM];
__device__ __align__(256) __nv_bfloat16 g_Wl[(size_t)N_DIM * K_DIM];

// ---------------- helpers ----------------
__device__ __forceinline__ uint32_t smem_u32_of(const void* p) {
    uint32_t a;
    asm("{ .reg .u64 t; cvta.to.shared.u64 t, %1; cvt.u32.u64 %0, t; }" : "=r"(a) : "l"(p));
    return a;
}
__device__ __forceinline__ void cp16(uint32_t dst, const void* src) {
    asm volatile("cp.async.cg.shared.global [%0], [%1], 16;" :: "r"(dst), "l"(src) : "memory");
}
__device__ __forceinline__ void ldsm4(uint32_t* r, uint32_t addr) {
    asm volatile("ldmatrix.sync.aligned.m8n8.x4.shared.b16 {%0,%1,%2,%3}, [%4];"
                 : "=r"(r[0]), "=r"(r[1]), "=r"(r[2]), "=r"(r[3]) : "r"(addr));
}
__device__ __forceinline__ void mma16816(float* d, const uint32_t* a, const uint32_t* b) {
    asm volatile(
        "mma.sync.aligned.m16n8k16.row.col.f32.bf16.bf16.f32 "
        "{%0,%1,%2,%3}, {%4,%5,%6,%7}, {%8,%9}, {%0,%1,%2,%3};"
        : "+f"(d[0]), "+f"(d[1]), "+f"(d[2]), "+f"(d[3])
        : "r"(a[0]), "r"(a[1]), "r"(a[2]), "r"(a[3]), "r"(b[0]), "r"(b[1]));
}
// 16B-chunk XOR swizzle: chunk' = c ^ ((row>>1)&3); makes every ldmatrix
// 8-row phase hit 8 distinct 16B banks with a 64B row stride.
__device__ __forceinline__ uint32_t chswz(int row, int c) {
    return (uint32_t)(row * 64 + ((c ^ ((row >> 1) & 3)) << 4));
}

// load one K-slab (A 128x32, W 256x32 bf16) into a pipeline stage
__device__ __forceinline__ void load_slab(uint32_t smem_u32, int stage, int s,
                                          int i0, int n0, int tid) {
    const int term = s / NSLAB_PER_TERM;                 // 0: Ah*Wh 1: Al*Wh 2: Ah*Wl
    const int kk   = (s - term * NSLAB_PER_TERM) * BK;
    const __nv_bfloat16* Asrc = (term == 1) ? g_Al : g_Ah;
    const __nv_bfloat16* Wsrc = (term == 2) ? g_Wl : g_Wh;
    const uint32_t stA = smem_u32 + stage * STAGE_BYTES;
    const uint32_t stB = stA + A_BYTES;
    #pragma unroll
    for (int i = 0; i < 2; i++) {                        // A: 512 chunks of 16B
        int j = tid + 256 * i, r = j >> 2, c = j & 3;
        cp16(stA + chswz(r, c), Asrc + (size_t)(i0 + r) * K_DIM + kk + c * 8);
    }
    #pragma unroll
    for (int i = 0; i < 4; i++) {                        // W: 1024 chunks
        int j = tid + 256 * i, r = j >> 2, c = j & 3;
        cp16(stB + chswz(r, c), Wsrc + (size_t)(n0 + r) * K_DIM + kk + c * 8);
    }
    asm volatile("cp.async.commit_group;" ::: "memory");
}

// ---------------- GEMM kernel ----------------
__global__ __launch_bounds__(256, 1)
void gemm_kernel(const int* __restrict__ ids, float* __restrict__ out)
{
    extern __shared__ char smem[];
    const uint32_t smem_u32 = smem_u32_of(smem);
    const int tid = threadIdx.x;
    const int wid = tid >> 5;
    const int lid = tid & 31;
    const int n0  = blockIdx.x * BN;
    const int i0  = blockIdx.y * BM;
    const int wm  = wid >> 2;            // 0..1 (64-row slab)
    const int wn  = wid & 3;             // 0..3 (64-col slab)

    // fully-invalid token tile -> zeros, skip GEMM
    int v = 0;
    if (tid < BM) { int id = ids[i0 + tid]; v = (id >= 0 && id < NUM_ITEMS_C); }
    if (!__syncthreads_or(v)) {
        const float4 z = make_float4(0.f, 0.f, 0.f, 0.f);
        #pragma unroll
        for (int i = 0; i < 32; i++) {
            int j = tid + 256 * i;       // 8192 float4s
            int r = j >> 6, cq = j & 63;
            *(float4*)&out[(size_t)(i0 + r) * N_DIM + n0 + cq * 4] = z;
        }
        return;
    }

    float acc[4][8][4];
    #pragma unroll
    for (int mf = 0; mf < 4; mf++)
        #pragma unroll
        for (int nf = 0; nf < 8; nf++)
            #pragma unroll
            for (int q = 0; q < 4; q++) acc[mf][nf][q] = 0.f;

    // prologue: stages 0..2
    load_slab(smem_u32, 0, 0, i0, n0, tid);
    load_slab(smem_u32, 1, 1, i0, n0, tid);
    load_slab(smem_u32, 2, 2, i0, n0, tid);

    for (int s = 0; s < NSLAB; ++s) {
        if (s < NSLAB - 2)      asm volatile("cp.async.wait_group 2;" ::: "memory");
        else if (s < NSLAB - 1) asm volatile("cp.async.wait_group 1;" ::: "memory");
        else                    asm volatile("cp.async.wait_group 0;" ::: "memory");
        __syncthreads();

        if (s + 3 < NSLAB)
            load_slab(smem_u32, (s + 3) & 3, s + 3, i0, n0, tid);

        const uint32_t stA = smem_u32 + (s & 3) * STAGE_BYTES;
        const uint32_t stB = stA + A_BYTES;

        #pragma unroll
        for (int kf = 0; kf < 2; kf++) {
            uint32_t a[4][4], b[4][4];
            #pragma unroll
            for (int mf = 0; mf < 4; mf++) {
                // x4 covers rows [base,base+16), k halves via chunk pair
                int row = wm * 64 + mf * 16 + (lid & 7) + ((lid >> 3) & 1) * 8;
                int ch  = 2 * kf + (lid >> 4);
                ldsm4(a[mf], stA + chswz(row, ch));
            }
            #pragma unroll
            for (int p = 0; p < 4; p++) {
                int row = wn * 64 + p * 16 + (lid & 7) + (lid >> 4) * 8;
                int ch  = 2 * kf + ((lid >> 3) & 1);
                ldsm4(b[p], stB + chswz(row, ch));
            }
            #pragma unroll
            for (int mf = 0; mf < 4; mf++)
                #pragma unroll
                for (int nf = 0; nf < 8; nf++)
                    mma16816(acc[mf][nf], a[mf], &b[nf >> 1][(nf & 1) * 2]);
        }
    }
    __syncthreads();

    // epilogue: direct register -> gmem (invalid rows computed 0 already)
    const int g = lid >> 2, t = lid & 3;
    #pragma unroll
    for (int mf = 0; mf < 4; mf++) {
        const size_t r0 = (size_t)(i0 + wm * 64 + mf * 16 + g);
        #pragma unroll
        for (int nf = 0; nf < 8; nf++) {
            const int col = n0 + wn * 64 + nf * 8 + t * 2;
            *(float2*)&out[r0 * N_DIM + col]       = make_float2(acc[mf][nf][0], acc[mf][nf][1]);
            *(float2*)&out[(r0 + 8) * N_DIM + col] = make_float2(acc[mf][nf][2], acc[mf][nf][3]);
        }
    }
}

// ---------------- pre-pass kernels ----------------
__device__ __forceinline__ void split4_store(float4 x, __nv_bfloat16* ph, __nv_bfloat16* pl) {
    __nv_bfloat16 h0 = __float2bfloat16(x.x), h1 = __float2bfloat16(x.y);
    __nv_bfloat16 h2 = __float2bfloat16(x.z), h3 = __float2bfloat16(x.w);
    __nv_bfloat16 l0 = __float2bfloat16(x.x - __bfloat162float(h0));
    __nv_bfloat16 l1 = __float2bfloat16(x.y - __bfloat162float(h1));
    __nv_bfloat16 l2 = __float2bfloat16(x.z - __bfloat162float(h2));
    __nv_bfloat16 l3 = __float2bfloat16(x.w - __bfloat162float(h3));
    union { __nv_bfloat16 b[4]; uint2 u; } uh, ul;
    uh.b[0] = h0; uh.b[1] = h1; uh.b[2] = h2; uh.b[3] = h3;
    ul.b[0] = l0; ul.b[1] = l1; ul.b[2] = l2; ul.b[3] = l3;
    *(uint2*)ph = uh.u;
    *(uint2*)pl = ul.u;
}

__global__ void convert_w_kernel(const float* __restrict__ W) {
    const int n = blockIdx.x;
    const int k = threadIdx.x * 4;              // 288 threads cover K=1152
    const size_t o = (size_t)n * K_DIM + k;
    split4_store(*(const float4*)&W[o], g_Wh + o, g_Wl + o);
}

__global__ void gather_kernel(const int* __restrict__ ids,
                              const float* __restrict__ E,
                              const float* __restrict__ V) {
    const int i = blockIdx.x;
    const int k = threadIdx.x * 4;
    const int id = ids[i];
    float4 x;
    if (id >= 0 && id < NUM_ITEMS_C) {
        x = (k < D_SEM_DIM)
            ? *(const float4*)&E[(size_t)id * D_SEM_DIM + k]
            : *(const float4*)&V[(size_t)id * D_PROMPT_DIM + (k - D_SEM_DIM)];
    } else {
        x = make_float4(0.f, 0.f, 0.f, 0.f);
    }
    const size_t o = (size_t)i * K_DIM + k;
    split4_store(x, g_Ah + o, g_Al + o);
}

__global__ void meta_kernel(const int* __restrict__ ids, float* __restrict__ out) {
    int i = blockIdx.x * 256 + threadIdx.x;
    if (i < TOKENS) {
        int id = ids[i];
        bool valid = (id >= 0 && id < NUM_ITEMS_C);
        const size_t base = (size_t)TOKENS * N_DIM;
        out[base + i]          = valid ? 1.0f : 0.0f;        // amask
        out[base + TOKENS + i] = valid ? (float)id : -1.0f;  // tok_item_ids
    }
}

extern "C" void kernel_launch(void* const* d_in, const int* in_sizes, int n_in,
                              void* d_out, int out_size)
{
    const int*   ids      = (const int*)  d_in[0];
    const float* E_sem    = (const float*)d_in[2];
    const float* v_prompt = (const float*)d_in[3];
    const float* W        = (const float*)d_in[4];
    float*       out      = (float*)d_out;

    static bool attr_set = false;
    if (!attr_set) {
        cudaFuncSetAttribute(gemm_kernel, cudaFuncAttributeMaxDynamicSharedMemorySize, SMEM_TOTAL);
        attr_set = true;
    }

    convert_w_kernel<<<N_DIM, 288>>>(W);
    gather_kernel<<<TOKENS, 288>>>(ids, E_sem, v_prompt);
    dim3 grid(N_DIM / BN, TOKENS / BM);   // (8, 100)
    gemm_kernel<<<grid, 256, SMEM_TOTAL>>>(ids, out);
    meta_kernel<<<(TOKENS + 255) / 256, 256>>>(ids, out);
}

// round 7
// speedup vs baseline: 6.1298x; 1.8859x over previous
#include <cuda_runtime.h>
#include <cuda_bf16.h>
#include <cstdint>

// Problem constants
#define TOKENS       12800
#define K_DIM        1152
#define D_SEM_DIM    768
#define D_PROMPT_DIM 384
#define N_DIM        2048
#define NUM_ITEMS_C  100000

// GEMM tiling (virtual K = 3 * K_DIM via hi/lo split terms)
#define BM      128
#define BN      256
#define BK      64
#define NSLAB_PER_TERM (K_DIM / BK)        // 18
#define NSLAB   (3 * NSLAB_PER_TERM)       // 54
#define STAGES  4

#define A_BYTES     (BM * BK * 2)          // 16384 (row stride 128 B)
#define B_BYTES     (BN * BK * 2)          // 32768
#define STAGE_BYTES (A_BYTES + B_BYTES)    // 49152
#define SMEM_TOTAL  (STAGES * STAGE_BYTES) // 196608

// bf16 hi/lo splits: A is gathered+compacted (valid tokens only), W full
__device__ __align__(256) __nv_bfloat16 g_Ah[(size_t)TOKENS * K_DIM];
__device__ __align__(256) __nv_bfloat16 g_Al[(size_t)TOKENS * K_DIM];
__device__ __align__(256) __nv_bfloat16 g_Wh[(size_t)N_DIM * K_DIM];
__device__ __align__(256) __nv_bfloat16 g_Wl[(size_t)N_DIM * K_DIM];
// compaction state
__device__ int g_count;
__device__ int g_slot[TOKENS];   // orig token -> compacted slot (-1 invalid)
__device__ int g_c2o[TOKENS];    // compacted slot -> orig token

// ---------------- helpers ----------------
__device__ __forceinline__ uint32_t smem_u32_of(const void* p) {
    uint32_t a;
    asm("{ .reg .u64 t; cvta.to.shared.u64 t, %1; cvt.u32.u64 %0, t; }" : "=r"(a) : "l"(p));
    return a;
}
__device__ __forceinline__ void cp16(uint32_t dst, const void* src) {
    asm volatile("cp.async.cg.shared.global [%0], [%1], 16;" :: "r"(dst), "l"(src) : "memory");
}
__device__ __forceinline__ void ldsm4(uint32_t* r, uint32_t addr) {
    asm volatile("ldmatrix.sync.aligned.m8n8.x4.shared.b16 {%0,%1,%2,%3}, [%4];"
                 : "=r"(r[0]), "=r"(r[1]), "=r"(r[2]), "=r"(r[3]) : "r"(addr));
}
__device__ __forceinline__ void mma16816(float* d, const uint32_t* a, const uint32_t* b) {
    asm volatile(
        "mma.sync.aligned.m16n8k16.row.col.f32.bf16.bf16.f32 "
        "{%0,%1,%2,%3}, {%4,%5,%6,%7}, {%8,%9}, {%0,%1,%2,%3};"
        : "+f"(d[0]), "+f"(d[1]), "+f"(d[2]), "+f"(d[3])
        : "r"(a[0]), "r"(a[1]), "r"(a[2]), "r"(a[3]), "r"(b[0]), "r"(b[1]));
}
// 128B-row swizzle: chunk' = c ^ (row & 7); every ldmatrix 8-row phase hits
// 8 distinct 16B banks.
__device__ __forceinline__ uint32_t chswz(int row, int c) {
    return (uint32_t)(row * 128 + ((c ^ (row & 7)) << 4));
}

// load one K-slab (A 128x64, W 256x64 bf16) into a pipeline stage
__device__ __forceinline__ void load_slab(uint32_t smem_u32, int stage, int s,
                                          int i0, int n0, int tid) {
    const int term = s / NSLAB_PER_TERM;                 // 0: Ah*Wh 1: Al*Wh 2: Ah*Wl
    const int kk   = (s - term * NSLAB_PER_TERM) * BK;
    const __nv_bfloat16* Asrc = (term == 1) ? g_Al : g_Ah;
    const __nv_bfloat16* Wsrc = (term == 2) ? g_Wl : g_Wh;
    const uint32_t stA = smem_u32 + stage * STAGE_BYTES;
    const uint32_t stB = stA + A_BYTES;
    #pragma unroll
    for (int i = 0; i < 4; i++) {                        // A: 1024 chunks of 16B
        int j = tid + 256 * i, r = j >> 3, c = j & 7;
        cp16(stA + chswz(r, c), Asrc + (size_t)(i0 + r) * K_DIM + kk + c * 8);
    }
    #pragma unroll
    for (int i = 0; i < 8; i++) {                        // W: 2048 chunks
        int j = tid + 256 * i, r = j >> 3, c = j & 7;
        cp16(stB + chswz(r, c), Wsrc + (size_t)(n0 + r) * K_DIM + kk + c * 8);
    }
    asm volatile("cp.async.commit_group;" ::: "memory");
}

// ---------------- GEMM kernel (over compacted valid rows) ----------------
__global__ __launch_bounds__(256, 1)
void gemm_kernel(float* __restrict__ out)
{
    const int n_valid = g_count;
    const int i0 = blockIdx.y * BM;      // compacted-row tile start
    if (i0 >= n_valid) return;           // surplus tile: nothing to compute

    extern __shared__ char smem[];
    const uint32_t smem_u32 = smem_u32_of(smem);
    const int tid = threadIdx.x;
    const int wid = tid >> 5;
    const int lid = tid & 31;
    const int n0  = blockIdx.x * BN;
    const int wm  = wid >> 2;            // 0..1 (64-row slab)
    const int wn  = wid & 3;             // 0..3 (64-col slab)

    __shared__ int s_orig[BM];
    if (tid < BM)
        s_orig[tid] = (i0 + tid < n_valid) ? g_c2o[i0 + tid] : -1;

    float acc[4][8][4];
    #pragma unroll
    for (int mf = 0; mf < 4; mf++)
        #pragma unroll
        for (int nf = 0; nf < 8; nf++)
            #pragma unroll
            for (int q = 0; q < 4; q++) acc[mf][nf][q] = 0.f;

    // prologue: stages 0..2  (rows >= n_valid read never-written zeros; harmless)
    load_slab(smem_u32, 0, 0, i0, n0, tid);
    load_slab(smem_u32, 1, 1, i0, n0, tid);
    load_slab(smem_u32, 2, 2, i0, n0, tid);

    for (int s = 0; s < NSLAB; ++s) {
        if (s < NSLAB - 2)      asm volatile("cp.async.wait_group 2;" ::: "memory");
        else if (s < NSLAB - 1) asm volatile("cp.async.wait_group 1;" ::: "memory");
        else                    asm volatile("cp.async.wait_group 0;" ::: "memory");
        __syncthreads();

        if (s + 3 < NSLAB)
            load_slab(smem_u32, (s + 3) & 3, s + 3, i0, n0, tid);

        const uint32_t stA = smem_u32 + (s & 3) * STAGE_BYTES;
        const uint32_t stB = stA + A_BYTES;

        #pragma unroll
        for (int kf = 0; kf < 4; kf++) {
            uint32_t a[4][4], b[4][4];
            #pragma unroll
            for (int mf = 0; mf < 4; mf++) {
                int row = wm * 64 + mf * 16 + (lid & 7) + ((lid >> 3) & 1) * 8;
                int ch  = 2 * kf + (lid >> 4);
                ldsm4(a[mf], stA + chswz(row, ch));
            }
            #pragma unroll
            for (int p = 0; p < 4; p++) {
                int row = wn * 64 + p * 16 + (lid & 7) + (lid >> 4) * 8;
                int ch  = 2 * kf + ((lid >> 3) & 1);
                ldsm4(b[p], stB + chswz(row, ch));
            }
            #pragma unroll
            for (int mf = 0; mf < 4; mf++)
                #pragma unroll
                for (int nf = 0; nf < 8; nf++)
                    mma16816(acc[mf][nf], a[mf], &b[nf >> 1][(nf & 1) * 2]);
        }
    }
    __syncthreads();

    // epilogue: scatter compacted rows back to original token rows
    const int g = lid >> 2, t = lid & 3;
    #pragma unroll
    for (int mf = 0; mf < 4; mf++) {
        const int r0 = wm * 64 + mf * 16 + g;
        const int o0 = s_orig[r0];
        const int o1 = s_orig[r0 + 8];
        #pragma unroll
        for (int nf = 0; nf < 8; nf++) {
            const int col = n0 + wn * 64 + nf * 8 + t * 2;
            if (o0 >= 0)
                *(float2*)&out[(size_t)o0 * N_DIM + col] =
                    make_float2(acc[mf][nf][0], acc[mf][nf][1]);
            if (o1 >= 0)
                *(float2*)&out[(size_t)o1 * N_DIM + col] =
                    make_float2(acc[mf][nf][2], acc[mf][nf][3]);
        }
    }
}

// ---------------- pre-pass kernels ----------------
__device__ __forceinline__ void split4_store(float4 x, __nv_bfloat16* ph, __nv_bfloat16* pl) {
    __nv_bfloat16 h0 = __float2bfloat16(x.x), h1 = __float2bfloat16(x.y);
    __nv_bfloat16 h2 = __float2bfloat16(x.z), h3 = __float2bfloat16(x.w);
    __nv_bfloat16 l0 = __float2bfloat16(x.x - __bfloat162float(h0));
    __nv_bfloat16 l1 = __float2bfloat16(x.y - __bfloat162float(h1));
    __nv_bfloat16 l2 = __float2bfloat16(x.z - __bfloat162float(h2));
    __nv_bfloat16 l3 = __float2bfloat16(x.w - __bfloat162float(h3));
    union { __nv_bfloat16 b[4]; uint2 u; } uh, ul;
    uh.b[0] = h0; uh.b[1] = h1; uh.b[2] = h2; uh.b[3] = h3;
    ul.b[0] = l0; ul.b[1] = l1; ul.b[2] = l2; ul.b[3] = l3;
    *(uint2*)ph = uh.u;
    *(uint2*)pl = ul.u;
}

__global__ void convert_w_kernel(const float* __restrict__ W) {
    if (blockIdx.x == 0 && threadIdx.x == 0) g_count = 0;   // reset for compact pass
    const int n = blockIdx.x;
    const int k = threadIdx.x * 4;              // 288 threads cover K=1152
    const size_t o = (size_t)n * K_DIM + k;
    split4_store(*(const float4*)&W[o], g_Wh + o, g_Wl + o);
}

// assign compacted slots + write amask / tok_item_ids
__global__ void compact_kernel(const int* __restrict__ ids, float* __restrict__ out) {
    int i = blockIdx.x * 256 + threadIdx.x;
    if (i >= TOKENS) return;
    int id = ids[i];
    bool valid = (id >= 0 && id < NUM_ITEMS_C);
    const size_t base = (size_t)TOKENS * N_DIM;
    out[base + i]          = valid ? 1.0f : 0.0f;
    out[base + TOKENS + i] = valid ? (float)id : -1.0f;
    if (valid) {
        int s = atomicAdd(&g_count, 1);
        g_slot[i] = s;
        g_c2o[s] = i;
    } else {
        g_slot[i] = -1;
    }
}

// gather valid tokens into compacted rows, bf16-split
__global__ void gather_kernel(const int* __restrict__ ids,
                              const float* __restrict__ E,
                              const float* __restrict__ V) {
    const int i = blockIdx.x;
    const int slot = g_slot[i];
    if (slot < 0) return;
    const int k = threadIdx.x * 4;
    const int id = ids[i];
    float4 x = (k < D_SEM_DIM)
        ? *(const float4*)&E[(size_t)id * D_SEM_DIM + k]
        : *(const float4*)&V[(size_t)id * D_PROMPT_DIM + (k - D_SEM_DIM)];
    const size_t o = (size_t)slot * K_DIM + k;
    split4_store(x, g_Ah + o, g_Al + o);
}

// zero the embeds rows of invalid tokens
__global__ void zero_invalid_kernel(const int* __restrict__ ids, float* __restrict__ out) {
    const int i = blockIdx.x;
    int id = ids[i];
    if (id >= 0 && id < NUM_ITEMS_C) return;
    const float4 z = make_float4(0.f, 0.f, 0.f, 0.f);
    float* row = out + (size_t)i * N_DIM;
    const int t = threadIdx.x;
    *(float4*)&row[t * 8]     = z;
    *(float4*)&row[t * 8 + 4] = z;
}

extern "C" void kernel_launch(void* const* d_in, const int* in_sizes, int n_in,
                              void* d_out, int out_size)
{
    const int*   ids      = (const int*)  d_in[0];
    const float* E_sem    = (const float*)d_in[2];
    const float* v_prompt = (const float*)d_in[3];
    const float* W        = (const float*)d_in[4];
    float*       out      = (float*)d_out;

    static bool attr_set = false;
    if (!attr_set) {
        cudaFuncSetAttribute(gemm_kernel, cudaFuncAttributeMaxDynamicSharedMemorySize, SMEM_TOTAL);
        attr_set = true;
    }

    convert_w_kernel<<<N_DIM, 288>>>(W);                         // also resets g_count
    compact_kernel<<<(TOKENS + 255) / 256, 256>>>(ids, out);     // slots + amask/tok
    gather_kernel<<<TOKENS, 288>>>(ids, E_sem, v_prompt);        // compacted A split
    zero_invalid_kernel<<<TOKENS, 256>>>(ids, out);              // invalid embed rows = 0
    dim3 grid(N_DIM / BN, TOKENS / BM);                          // (8, 100); surplus tiles exit
    gemm_kernel<<<grid, 256, SMEM_TOTAL>>>(out);
}

// round 8
// speedup vs baseline: 8.3964x; 1.3698x over previous
#include <cuda_runtime.h>
#include <cuda_fp16.h>
#include <cstdint>

// Problem constants
#define TOKENS       12800
#define K_DIM        1152
#define D_SEM_DIM    768
#define D_PROMPT_DIM 384
#define N_DIM        2048
#define NUM_ITEMS_C  100000

// GEMM tiling (virtual K = 2 * K_DIM: terms Ah*W and Al*W, fp16 split of A)
#define BM      128
#define BN      256
#define BK      64
#define NSLAB_PER_TERM (K_DIM / BK)        // 18
#define NSLAB   (2 * NSLAB_PER_TERM)       // 36
#define STAGES  4

#define A_BYTES     (BM * BK * 2)          // 16384 (row stride 128 B)
#define B_BYTES     (BN * BK * 2)          // 32768
#define STAGE_BYTES (A_BYTES + B_BYTES)    // 49152
#define SMEM_TOTAL  (STAGES * STAGE_BYTES) // 196608

// fp16 operands: A gathered+compacted hi/lo split, W single fp16
__device__ __align__(256) __half g_Ah[(size_t)TOKENS * K_DIM];
__device__ __align__(256) __half g_Al[(size_t)TOKENS * K_DIM];
__device__ __align__(256) __half g_Wh[(size_t)N_DIM * K_DIM];
// compaction state
__device__ int g_count;
__device__ int g_slot[TOKENS];   // orig token -> compacted slot (-1 invalid)
__device__ int g_c2o[TOKENS];    // compacted slot -> orig token

// ---------------- helpers ----------------
__device__ __forceinline__ uint32_t smem_u32_of(const void* p) {
    uint32_t a;
    asm("{ .reg .u64 t; cvta.to.shared.u64 t, %1; cvt.u32.u64 %0, t; }" : "=r"(a) : "l"(p));
    return a;
}
__device__ __forceinline__ void cp16(uint32_t dst, const void* src) {
    asm volatile("cp.async.cg.shared.global [%0], [%1], 16;" :: "r"(dst), "l"(src) : "memory");
}
__device__ __forceinline__ void ldsm4(uint32_t* r, uint32_t addr) {
    asm volatile("ldmatrix.sync.aligned.m8n8.x4.shared.b16 {%0,%1,%2,%3}, [%4];"
                 : "=r"(r[0]), "=r"(r[1]), "=r"(r[2]), "=r"(r[3]) : "r"(addr));
}
__device__ __forceinline__ void mma16816(float* d, const uint32_t* a, const uint32_t* b) {
    asm volatile(
        "mma.sync.aligned.m16n8k16.row.col.f32.f16.f16.f32 "
        "{%0,%1,%2,%3}, {%4,%5,%6,%7}, {%8,%9}, {%0,%1,%2,%3};"
        : "+f"(d[0]), "+f"(d[1]), "+f"(d[2]), "+f"(d[3])
        : "r"(a[0]), "r"(a[1]), "r"(a[2]), "r"(a[3]), "r"(b[0]), "r"(b[1]));
}
// 128B-row swizzle: chunk' = c ^ (row & 7); every ldmatrix 8-row phase hits
// 8 distinct 16B banks.
__device__ __forceinline__ uint32_t chswz(int row, int c) {
    return (uint32_t)(row * 128 + ((c ^ (row & 7)) << 4));
}

// load one K-slab (A 128x64, W 256x64 fp16) into a pipeline stage
__device__ __forceinline__ void load_slab(uint32_t smem_u32, int stage, int s,
                                          int i0, int n0, int tid) {
    const int term = (s >= NSLAB_PER_TERM);              // 0: Ah*W  1: Al*W
    const int kk   = (s - term * NSLAB_PER_TERM) * BK;
    const __half* Asrc = term ? g_Al : g_Ah;
    const uint32_t stA = smem_u32 + stage * STAGE_BYTES;
    const uint32_t stB = stA + A_BYTES;
    #pragma unroll
    for (int i = 0; i < 4; i++) {                        // A: 1024 chunks of 16B
        int j = tid + 256 * i, r = j >> 3, c = j & 7;
        cp16(stA + chswz(r, c), Asrc + (size_t)(i0 + r) * K_DIM + kk + c * 8);
    }
    #pragma unroll
    for (int i = 0; i < 8; i++) {                        // W: 2048 chunks
        int j = tid + 256 * i, r = j >> 3, c = j & 7;
        cp16(stB + chswz(r, c), g_Wh + (size_t)(n0 + r) * K_DIM + kk + c * 8);
    }
    asm volatile("cp.async.commit_group;" ::: "memory");
}

// ---------------- GEMM kernel (over compacted valid rows) ----------------
__global__ __launch_bounds__(256, 1)
void gemm_kernel(float* __restrict__ out)
{
    const int n_valid = g_count;
    const int i0 = blockIdx.y * BM;      // compacted-row tile start
    if (i0 >= n_valid) return;           // surplus tile: nothing to compute

    extern __shared__ char smem[];
    const uint32_t smem_u32 = smem_u32_of(smem);
    const int tid = threadIdx.x;
    const int wid = tid >> 5;
    const int lid = tid & 31;
    const int n0  = blockIdx.x * BN;
    const int wm  = wid >> 2;            // 0..1 (64-row slab)
    const int wn  = wid & 3;             // 0..3 (64-col slab)

    __shared__ int s_orig[BM];
    if (tid < BM)
        s_orig[tid] = (i0 + tid < n_valid) ? g_c2o[i0 + tid] : -1;

    float acc[4][8][4];
    #pragma unroll
    for (int mf = 0; mf < 4; mf++)
        #pragma unroll
        for (int nf = 0; nf < 8; nf++)
            #pragma unroll
            for (int q = 0; q < 4; q++) acc[mf][nf][q] = 0.f;

    // prologue: stages 0..2
    load_slab(smem_u32, 0, 0, i0, n0, tid);
    load_slab(smem_u32, 1, 1, i0, n0, tid);
    load_slab(smem_u32, 2, 2, i0, n0, tid);

    for (int s = 0; s < NSLAB; ++s) {
        if (s < NSLAB - 2)      asm volatile("cp.async.wait_group 2;" ::: "memory");
        else if (s < NSLAB - 1) asm volatile("cp.async.wait_group 1;" ::: "memory");
        else                    asm volatile("cp.async.wait_group 0;" ::: "memory");
        __syncthreads();

        if (s + 3 < NSLAB)
            load_slab(smem_u32, (s + 3) & 3, s + 3, i0, n0, tid);

        const uint32_t stA = smem_u32 + (s & 3) * STAGE_BYTES;
        const uint32_t stB = stA + A_BYTES;

        #pragma unroll
        for (int kf = 0; kf < 4; kf++) {
            uint32_t a[4][4], b[4][4];
            #pragma unroll
            for (int mf = 0; mf < 4; mf++) {
                int row = wm * 64 + mf * 16 + (lid & 7) + ((lid >> 3) & 1) * 8;
                int ch  = 2 * kf + (lid >> 4);
                ldsm4(a[mf], stA + chswz(row, ch));
            }
            #pragma unroll
            for (int p = 0; p < 4; p++) {
                int row = wn * 64 + p * 16 + (lid & 7) + (lid >> 4) * 8;
                int ch  = 2 * kf + ((lid >> 3) & 1);
                ldsm4(b[p], stB + chswz(row, ch));
            }
            #pragma unroll
            for (int mf = 0; mf < 4; mf++)
                #pragma unroll
                for (int nf = 0; nf < 8; nf++)
                    mma16816(acc[mf][nf], a[mf], &b[nf >> 1][(nf & 1) * 2]);
        }
    }
    __syncthreads();

    // epilogue: scatter compacted rows back to original token rows
    const int g = lid >> 2, t = lid & 3;
    #pragma unroll
    for (int mf = 0; mf < 4; mf++) {
        const int r0 = wm * 64 + mf * 16 + g;
        const int o0 = s_orig[r0];
        const int o1 = s_orig[r0 + 8];
        #pragma unroll
        for (int nf = 0; nf < 8; nf++) {
            const int col = n0 + wn * 64 + nf * 8 + t * 2;
            if (o0 >= 0)
                *(float2*)&out[(size_t)o0 * N_DIM + col] =
                    make_float2(acc[mf][nf][0], acc[mf][nf][1]);
            if (o1 >= 0)
                *(float2*)&out[(size_t)o1 * N_DIM + col] =
                    make_float2(acc[mf][nf][2], acc[mf][nf][3]);
        }
    }
}

// ---------------- pre-pass kernels ----------------
// fp16 hi/lo split of 4 floats
__device__ __forceinline__ void split4_store_hl(float4 x, __half* ph, __half* pl) {
    __half h0 = __float2half(x.x), h1 = __float2half(x.y);
    __half h2 = __float2half(x.z), h3 = __float2half(x.w);
    __half l0 = __float2half(x.x - __half2float(h0));
    __half l1 = __float2half(x.y - __half2float(h1));
    __half l2 = __float2half(x.z - __half2float(h2));
    __half l3 = __float2half(x.w - __half2float(h3));
    union { __half b[4]; uint2 u; } uh, ul;
    uh.b[0] = h0; uh.b[1] = h1; uh.b[2] = h2; uh.b[3] = h3;
    ul.b[0] = l0; ul.b[1] = l1; ul.b[2] = l2; ul.b[3] = l3;
    *(uint2*)ph = uh.u;
    *(uint2*)pl = ul.u;
}

__global__ void convert_w_kernel(const float* __restrict__ W) {
    if (blockIdx.x == 0 && threadIdx.x == 0) g_count = 0;   // reset for compact pass
    const int n = blockIdx.x;
    const int k = threadIdx.x * 4;              // 288 threads cover K=1152
    const size_t o = (size_t)n * K_DIM + k;
    float4 x = *(const float4*)&W[o];
    union { __half b[4]; uint2 u; } uh;
    uh.b[0] = __float2half(x.x); uh.b[1] = __float2half(x.y);
    uh.b[2] = __float2half(x.z); uh.b[3] = __float2half(x.w);
    *(uint2*)(g_Wh + o) = uh.u;
}

// assign compacted slots + write amask / tok_item_ids
__global__ void compact_kernel(const int* __restrict__ ids, float* __restrict__ out) {
    int i = blockIdx.x * 256 + threadIdx.x;
    if (i >= TOKENS) return;
    int id = ids[i];
    bool valid = (id >= 0 && id < NUM_ITEMS_C);
    const size_t base = (size_t)TOKENS * N_DIM;
    out[base + i]          = valid ? 1.0f : 0.0f;
    out[base + TOKENS + i] = valid ? (float)id : -1.0f;
    if (valid) {
        int s = atomicAdd(&g_count, 1);
        g_slot[i] = s;
        g_c2o[s] = i;
    } else {
        g_slot[i] = -1;
    }
}

// gather valid tokens into compacted rows, fp16 hi/lo split
__global__ void gather_kernel(const int* __restrict__ ids,
                              const float* __restrict__ E,
                              const float* __restrict__ V) {
    const int i = blockIdx.x;
    const int slot = g_slot[i];
    if (slot < 0) return;
    const int k = threadIdx.x * 4;
    const int id = ids[i];
    float4 x = (k < D_SEM_DIM)
        ? *(const float4*)&E[(size_t)id * D_SEM_DIM + k]
        : *(const float4*)&V[(size_t)id * D_PROMPT_DIM + (k - D_SEM_DIM)];
    const size_t o = (size_t)slot * K_DIM + k;
    split4_store_hl(x, g_Ah + o, g_Al + o);
}

// zero the embeds rows of invalid tokens
__global__ void zero_invalid_kernel(const int* __restrict__ ids, float* __restrict__ out) {
    const int i = blockIdx.x;
    int id = ids[i];
    if (id >= 0 && id < NUM_ITEMS_C) return;
    const float4 z = make_float4(0.f, 0.f, 0.f, 0.f);
    float* row = out + (size_t)i * N_DIM;
    const int t = threadIdx.x;
    *(float4*)&row[t * 8]     = z;
    *(float4*)&row[t * 8 + 4] = z;
}

extern "C" void kernel_launch(void* const* d_in, const int* in_sizes, int n_in,
                              void* d_out, int out_size)
{
    const int*   ids      = (const int*)  d_in[0];
    const float* E_sem    = (const float*)d_in[2];
    const float* v_prompt = (const float*)d_in[3];
    const float* W        = (const float*)d_in[4];
    float*       out      = (float*)d_out;

    static bool attr_set = false;
    if (!attr_set) {
        cudaFuncSetAttribute(gemm_kernel, cudaFuncAttributeMaxDynamicSharedMemorySize, SMEM_TOTAL);
        attr_set = true;
    }

    convert_w_kernel<<<N_DIM, 288>>>(W);                         // also resets g_count
    compact_kernel<<<(TOKENS + 255) / 256, 256>>>(ids, out);     // slots + amask/tok
    gather_kernel<<<TOKENS, 288>>>(ids, E_sem, v_prompt);        // compacted A split
    zero_invalid_kernel<<<TOKENS, 256>>>(ids, out);              // invalid embed rows = 0
    dim3 grid(N_DIM / BN, TOKENS / BM);                          // (8, 100); surplus tiles exit
    gemm_kernel<<<grid, 256, SMEM_TOTAL>>>(out);
}

// round 11
// speedup vs baseline: 13.7412x; 1.6365x over previous
#include <cuda_runtime.h>
#include <cuda_fp16.h>
#include <cstdint>

// Single-term fp16 GEMM over compacted valid tokens (R8 design, re-bench).
// D = fp16(A_gathered) * fp16(W), fp32 accumulate; invalid rows zero-filled.
//
// Problem constants
#define TOKENS       12800
#define K_DIM        1152
#define D_SEM_DIM    768
#define D_PROMPT_DIM 384
#define N_DIM        2048
#define NUM_ITEMS_C  100000

// GEMM tiling
#define BM      128
#define BN      256
#define BK      64
#define NSLAB   (K_DIM / BK)               // 18
#define STAGES  4

#define A_BYTES     (BM * BK * 2)          // 16384 (row stride 128 B)
#define B_BYTES     (BN * BK * 2)          // 32768
#define STAGE_BYTES (A_BYTES + B_BYTES)    // 49152
#define SMEM_TOTAL  (STAGES * STAGE_BYTES) // 196608

// fp16 operands: A gathered+compacted, W converted
__device__ __align__(256) __half g_Ah[(size_t)TOKENS * K_DIM];
__device__ __align__(256) __half g_Wh[(size_t)N_DIM * K_DIM];
// compaction state
__device__ int g_count;
__device__ int g_slot[TOKENS];   // orig token -> compacted slot (-1 invalid)
__device__ int g_c2o[TOKENS];    // compacted slot -> orig token

// ---------------- helpers ----------------
__device__ __forceinline__ uint32_t smem_u32_of(const void* p) {
    uint32_t a;
    asm("{ .reg .u64 t; cvta.to.shared.u64 t, %1; cvt.u32.u64 %0, t; }" : "=r"(a) : "l"(p));
    return a;
}
__device__ __forceinline__ void cp16(uint32_t dst, const void* src) {
    asm volatile("cp.async.cg.shared.global [%0], [%1], 16;" :: "r"(dst), "l"(src) : "memory");
}
__device__ __forceinline__ void ldsm4(uint32_t* r, uint32_t addr) {
    asm volatile("ldmatrix.sync.aligned.m8n8.x4.shared.b16 {%0,%1,%2,%3}, [%4];"
                 : "=r"(r[0]), "=r"(r[1]), "=r"(r[2]), "=r"(r[3]) : "r"(addr));
}
__device__ __forceinline__ void mma16816(float* d, const uint32_t* a, const uint32_t* b) {
    asm volatile(
        "mma.sync.aligned.m16n8k16.row.col.f32.f16.f16.f32 "
        "{%0,%1,%2,%3}, {%4,%5,%6,%7}, {%8,%9}, {%0,%1,%2,%3};"
        : "+f"(d[0]), "+f"(d[1]), "+f"(d[2]), "+f"(d[3])
        : "r"(a[0]), "r"(a[1]), "r"(a[2]), "r"(a[3]), "r"(b[0]), "r"(b[1]));
}
// 128B-row swizzle: chunk' = c ^ (row & 7); every ldmatrix 8-row phase hits
// 8 distinct 16B banks.
__device__ __forceinline__ uint32_t chswz(int row, int c) {
    return (uint32_t)(row * 128 + ((c ^ (row & 7)) << 4));
}

// load one K-slab (A 128x64, W 256x64 fp16) into a pipeline stage
__device__ __forceinline__ void load_slab(uint32_t smem_u32, int stage, int s,
                                          int i0, int n0, int tid) {
    const int kk = s * BK;
    const uint32_t stA = smem_u32 + stage * STAGE_BYTES;
    const uint32_t stB = stA + A_BYTES;
    #pragma unroll
    for (int i = 0; i < 4; i++) {                        // A: 1024 chunks of 16B
        int j = tid + 256 * i, r = j >> 3, c = j & 7;
        cp16(stA + chswz(r, c), g_Ah + (size_t)(i0 + r) * K_DIM + kk + c * 8);
    }
    #pragma unroll
    for (int i = 0; i < 8; i++) {                        // W: 2048 chunks
        int j = tid + 256 * i, r = j >> 3, c = j & 7;
        cp16(stB + chswz(r, c), g_Wh + (size_t)(n0 + r) * K_DIM + kk + c * 8);
    }
    asm volatile("cp.async.commit_group;" ::: "memory");
}

// ---------------- GEMM kernel (over compacted valid rows) ----------------
__global__ __launch_bounds__(256, 1)
void gemm_kernel(float* __restrict__ out)
{
    const int n_valid = g_count;
    const int i0 = blockIdx.y * BM;      // compacted-row tile start
    if (i0 >= n_valid) return;           // surplus tile: nothing to compute

    extern __shared__ char smem[];
    const uint32_t smem_u32 = smem_u32_of(smem);
    const int tid = threadIdx.x;
    const int wid = tid >> 5;
    const int lid = tid & 31;
    const int n0  = blockIdx.x * BN;
    const int wm  = wid >> 2;            // 0..1 (64-row slab)
    const int wn  = wid & 3;             // 0..3 (64-col slab)

    __shared__ int s_orig[BM];
    if (tid < BM)
        s_orig[tid] = (i0 + tid < n_valid) ? g_c2o[i0 + tid] : -1;

    float acc[4][8][4];
    #pragma unroll
    for (int mf = 0; mf < 4; mf++)
        #pragma unroll
        for (int nf = 0; nf < 8; nf++)
            #pragma unroll
            for (int q = 0; q < 4; q++) acc[mf][nf][q] = 0.f;

    // prologue: stages 0..2
    load_slab(smem_u32, 0, 0, i0, n0, tid);
    load_slab(smem_u32, 1, 1, i0, n0, tid);
    load_slab(smem_u32, 2, 2, i0, n0, tid);

    for (int s = 0; s < NSLAB; ++s) {
        if (s < NSLAB - 2)      asm volatile("cp.async.wait_group 2;" ::: "memory");
        else if (s < NSLAB - 1) asm volatile("cp.async.wait_group 1;" ::: "memory");
        else                    asm volatile("cp.async.wait_group 0;" ::: "memory");
        __syncthreads();

        if (s + 3 < NSLAB)
            load_slab(smem_u32, (s + 3) & 3, s + 3, i0, n0, tid);

        const uint32_t stA = smem_u32 + (s & 3) * STAGE_BYTES;
        const uint32_t stB = stA + A_BYTES;

        #pragma unroll
        for (int kf = 0; kf < 4; kf++) {
            uint32_t a[4][4], b[4][4];
            #pragma unroll
            for (int mf = 0; mf < 4; mf++) {
                int row = wm * 64 + mf * 16 + (lid & 7) + ((lid >> 3) & 1) * 8;
                int ch  = 2 * kf + (lid >> 4);
                ldsm4(a[mf], stA + chswz(row, ch));
            }
            #pragma unroll
            for (int p = 0; p < 4; p++) {
                int row = wn * 64 + p * 16 + (lid & 7) + (lid >> 4) * 8;
                int ch  = 2 * kf + ((lid >> 3) & 1);
                ldsm4(b[p], stB + chswz(row, ch));
            }
            #pragma unroll
            for (int mf = 0; mf < 4; mf++)
                #pragma unroll
                for (int nf = 0; nf < 8; nf++)
                    mma16816(acc[mf][nf], a[mf], &b[nf >> 1][(nf & 1) * 2]);
        }
    }
    __syncthreads();

    // epilogue: scatter compacted rows back to original token rows
    const int g = lid >> 2, t = lid & 3;
    #pragma unroll
    for (int mf = 0; mf < 4; mf++) {
        const int r0 = wm * 64 + mf * 16 + g;
        const int o0 = s_orig[r0];
        const int o1 = s_orig[r0 + 8];
        #pragma unroll
        for (int nf = 0; nf < 8; nf++) {
            const int col = n0 + wn * 64 + nf * 8 + t * 2;
            if (o0 >= 0)
                *(float2*)&out[(size_t)o0 * N_DIM + col] =
                    make_float2(acc[mf][nf][0], acc[mf][nf][1]);
            if (o1 >= 0)
                *(float2*)&out[(size_t)o1 * N_DIM + col] =
                    make_float2(acc[mf][nf][2], acc[mf][nf][3]);
        }
    }
}

// ---------------- pre-pass kernels ----------------
__device__ __forceinline__ void cvt4_store(float4 x, __half* ph) {
    union { __half b[4]; uint2 u; } uh;
    uh.b[0] = __float2half(x.x); uh.b[1] = __float2half(x.y);
    uh.b[2] = __float2half(x.z); uh.b[3] = __float2half(x.w);
    *(uint2*)ph = uh.u;
}

__global__ void convert_w_kernel(const float* __restrict__ W) {
    if (blockIdx.x == 0 && threadIdx.x == 0) g_count = 0;   // reset for compact pass
    const int n = blockIdx.x;
    const int k = threadIdx.x * 4;              // 288 threads cover K=1152
    const size_t o = (size_t)n * K_DIM + k;
    cvt4_store(*(const float4*)&W[o], g_Wh + o);
}

// assign compacted slots + write amask / tok_item_ids
__global__ void compact_kernel(const int* __restrict__ ids, float* __restrict__ out) {
    int i = blockIdx.x * 256 + threadIdx.x;
    if (i >= TOKENS) return;
    int id = ids[i];
    bool valid = (id >= 0 && id < NUM_ITEMS_C);
    const size_t base = (size_t)TOKENS * N_DIM;
    out[base + i]          = valid ? 1.0f : 0.0f;
    out[base + TOKENS + i] = valid ? (float)id : -1.0f;
    if (valid) {
        int s = atomicAdd(&g_count, 1);
        g_slot[i] = s;
        g_c2o[s] = i;
    } else {
        g_slot[i] = -1;
    }
}

// gather valid tokens into compacted rows, fp16
__global__ void gather_kernel(const int* __restrict__ ids,
                              const float* __restrict__ E,
                              const float* __restrict__ V) {
    const int i = blockIdx.x;
    const int slot = g_slot[i];
    if (slot < 0) return;
    const int k = threadIdx.x * 4;
    const int id = ids[i];
    float4 x = (k < D_SEM_DIM)
        ? *(const float4*)&E[(size_t)id * D_SEM_DIM + k]
        : *(const float4*)&V[(size_t)id * D_PROMPT_DIM + (k - D_SEM_DIM)];
    cvt4_store(x, g_Ah + (size_t)slot * K_DIM + k);
}

// zero the embeds rows of invalid tokens
__global__ void zero_invalid_kernel(const int* __restrict__ ids, float* __restrict__ out) {
    const int i = blockIdx.x;
    int id = ids[i];
    if (id >= 0 && id < NUM_ITEMS_C) return;
    const float4 z = make_float4(0.f, 0.f, 0.f, 0.f);
    float* row = out + (size_t)i * N_DIM;
    const int t = threadIdx.x;
    *(float4*)&row[t * 8]     = z;
    *(float4*)&row[t * 8 + 4] = z;
}

extern "C" void kernel_launch(void* const* d_in, const int* in_sizes, int n_in,
                              void* d_out, int out_size)
{
    const int*   ids      = (const int*)  d_in[0];
    const float* E_sem    = (const float*)d_in[2];
    const float* v_prompt = (const float*)d_in[3];
    const float* W        = (const float*)d_in[4];
    float*       out      = (float*)d_out;

    static bool attr_set = false;
    if (!attr_set) {
        cudaFuncSetAttribute(gemm_kernel, cudaFuncAttributeMaxDynamicSharedMemorySize, SMEM_TOTAL);
        attr_set = true;
    }

    convert_w_kernel<<<N_DIM, 288>>>(W);                         // also resets g_count
    compact_kernel<<<(TOKENS + 255) / 256, 256>>>(ids, out);     // slots + amask/tok
    gather_kernel<<<TOKENS, 288>>>(ids, E_sem, v_prompt);        // compacted fp16 A
    zero_invalid_kernel<<<TOKENS, 256>>>(ids, out);              // invalid embed rows = 0
    dim3 grid(N_DIM / BN, TOKENS / BM);                          // (8, 100); surplus tiles exit
    gemm_kernel<<<grid, 256, SMEM_TOTAL>>>(out);
}